// round 10
// baseline (speedup 1.0000x reference)
#include <cuda_runtime.h>
#include <cuda_fp16.h>
#include <math.h>
#include <stdint.h>

#define Bdim 64
#define Sdim 256
#define Idim 128
#define Hdim 128
#define UNF  6
#define EPSV 1e-8f

// ---------------- device scratch ----------------
// pair-packed recurrent params: index e = p*128 + d, p = src/2 (0..63)
__device__ __half2 g_RP1h[64*Hdim];  // (0.5*sigma[2p,d], 0.5*sigma[2p+1,d])
__device__ __half2 g_RCh [64*Hdim];  // (-0.5*sigma*mu) pairs
__device__ __half2 g_RWh [64*Hdim];  // (0.5*softplus(w)*erev) pairs
// pair-packed sensory params (fp16)
__device__ __half2 g_SP1[64*Hdim];
__device__ __half2 g_SC [64*Hdim];
__device__ __half2 g_SW [64*Hdim];
// epilogue matvec weights, [d][k] row-major fp16
__device__ __half  g_Ph[Hdim*Hdim];
__device__ __half  g_Sa[Hdim*Hdim];
__device__ float   g_KN[Hdim];
__device__ float   g_KD[Hdim];
__device__ float   g_CmT[Hdim];
__device__ float2  g_Sen[Bdim*Sdim*Hdim];   // per-(b,t,d): (num_s, den_s)

static __device__ __forceinline__ float ltc_softplus(float x) {
    return fmaxf(x, 0.f) + log1pf(expf(-fabsf(x)));
}
static __device__ __forceinline__ float ltc_tanh_f32(float x) {
    float y; asm("tanh.approx.f32 %0, %1;" : "=f"(y) : "f"(x)); return y;
}
static __device__ __forceinline__ __half2 ltc_tanh_h2(__half2 x) {
    uint32_t xi = *reinterpret_cast<uint32_t*>(&x);
    uint32_t yi;
    asm("tanh.approx.f16x2 %0, %1;" : "=r"(yi) : "r"(xi));
    return *reinterpret_cast<__half2*>(&yi);
}

// ---------------- precompute ----------------
__global__ void ltc_pre1(const float* __restrict__ sigma, const float* __restrict__ mu,
                         const float* __restrict__ w,     const float* __restrict__ erev,
                         const float* __restrict__ s_sigma, const float* __restrict__ s_mu,
                         const float* __restrict__ s_w,   const float* __restrict__ s_erev,
                         const float* __restrict__ input_w, const float* __restrict__ input_b,
                         const float* __restrict__ phase_W, const float* __restrict__ sa_W)
{
    int e = blockIdx.x * blockDim.x + threadIdx.x;
    if (e >= Hdim * Hdim) return;
    g_Ph[e] = __float2half(phase_W[e]);
    g_Sa[e] = __float2half(sa_W[e]);

    if (e < 64 * Hdim) {
        int p = e >> 7, d = e & 127;
        int s0 = 2 * p, s1 = 2 * p + 1;
        float sg0 = sigma[s0*Hdim+d], sg1 = sigma[s1*Hdim+d];
        g_RP1h[e] = __floats2half2_rn(0.5f*sg0, 0.5f*sg1);
        g_RCh [e] = __floats2half2_rn(-0.5f*sg0*mu[s0*Hdim+d], -0.5f*sg1*mu[s1*Hdim+d]);
        g_RWh [e] = __floats2half2_rn(0.5f*ltc_softplus(w[s0*Hdim+d])*erev[s0*Hdim+d],
                                      0.5f*ltc_softplus(w[s1*Hdim+d])*erev[s1*Hdim+d]);
        float ss0 = s_sigma[s0*Hdim+d], ss1 = s_sigma[s1*Hdim+d];
        g_SP1[e] = __floats2half2_rn(0.5f*ss0*input_w[s0], 0.5f*ss1*input_w[s1]);
        g_SC [e] = __floats2half2_rn(0.5f*ss0*(input_b[s0]-s_mu[s0*Hdim+d]),
                                     0.5f*ss1*(input_b[s1]-s_mu[s1*Hdim+d]));
        g_SW [e] = __floats2half2_rn(0.5f*ltc_softplus(s_w[s0*Hdim+d])*s_erev[s0*Hdim+d],
                                     0.5f*ltc_softplus(s_w[s1*Hdim+d])*s_erev[s1*Hdim+d]);
    }
}

__global__ void ltc_pre2(const float* __restrict__ gleak, const float* __restrict__ vleak,
                         const float* __restrict__ cm,
                         const float* __restrict__ w, const float* __restrict__ erev,
                         const float* __restrict__ s_w, const float* __restrict__ s_erev)
{
    int d = threadIdx.x;
    if (d >= Hdim) return;
    float Cn = 0.f, Cd = 0.f;
    for (int s = 0; s < Hdim; ++s) {
        float v = 0.5f * ltc_softplus(w[s*Hdim+d]) * erev[s*Hdim+d];
        Cn += v; Cd += fabsf(v);
    }
    for (int i = 0; i < Idim; ++i) {
        float v = 0.5f * ltc_softplus(s_w[i*Hdim+d]) * s_erev[i*Hdim+d];
        Cn += v; Cd += fabsf(v);
    }
    float gl  = ltc_softplus(gleak[d]);
    float cmt = ltc_softplus(cm[d]) * ((float)UNF / 1.0f);
    g_KN[d]  = gl * vleak[d] + Cn;
    g_KD[d]  = cmt + gl + Cd + EPSV;
    g_CmT[d] = cmt;
}

// ---------------- sensory precompute (parallel over all (b,t)) ----------------
#define SEN_SMEM 100608

__global__ __launch_bounds__(256, 1)
void ltc_sensory(const float* __restrict__ x)
{
    extern __shared__ char smem[];
    __half2* sP1 = (__half2*)smem;
    __half2* sC  = (__half2*)(smem + 32768);
    __half2* sW  = (__half2*)(smem + 65536);
    __half2* sxh = (__half2*)(smem + 98304);
    float*   red = (float*)(smem + 98560);

    const int tid = threadIdx.x;
    for (int i = tid; i < 64*Hdim; i += 256) {
        sP1[i] = g_SP1[i]; sC[i] = g_SC[i]; sW[i] = g_SW[i];
    }
    __syncthreads();

    const int d  = tid & 127;
    const int p0 = (tid >> 7) * 32;

    for (int item = blockIdx.x; item < Bdim*Sdim; item += gridDim.x) {
        if (tid < 64) {
            float2 x2 = ((const float2*)(x + (size_t)item * Idim))[tid];
            sxh[tid] = __floats2half2_rn(x2.x, x2.y);
        }
        __syncthreads();
        float qn = 0.f, qd = 0.f;
        #pragma unroll
        for (int i = 0; i < 32; ++i) {
            int e = (p0 + i) * Hdim + d;
            __half2 arg = __hfma2(sP1[e], sxh[p0 + i], sC[e]);
            float2 th = __half22float2(ltc_tanh_h2(arg));
            float2 wf = __half22float2(sW[e]);
            qn = fmaf(wf.x, th.x, qn); qn = fmaf(wf.y, th.y, qn);
            qd = fmaf(fabsf(wf.x), th.x, qd); qd = fmaf(fabsf(wf.y), th.y, qd);
        }
        red[tid] = qn;
        red[256 + tid] = qd;
        __syncthreads();
        if (tid < 128)
            g_Sen[(size_t)item * Hdim + tid] = make_float2(red[tid] + red[tid + 128],
                                                           red[256 + tid] + red[384 + tid]);
        __syncthreads();
    }
}

// ---------------- scan kernel: shuffle-state version -------------------------
// warp w: sb = w>>2 (src block), db = w&3 (dst block)
// thread: d = 32*db + lane  (dst of partials),  dp = 32*sb + lane (state owner)
// state v[dp] lives in registers, redundant x4 across db; exchanged via shfl.
// smem:
//   0      sPh  half [128 rows, pitch 130] 33280
//   33280  sSa  half [128 rows, pitch 130] 33280 -> 66560
//   66560  redA float2[512] 4096 -> 70656
//   70656  redB float2[512] 4096 -> 74752
#define SCAN_SMEM 74752
#define PH_PITCH 130
#define FULLMASK 0xffffffffu

__global__ __launch_bounds__(512, 1)
void ltc_scan(const float* __restrict__ h0,
              const float* __restrict__ amplitude, const float* __restrict__ omega,
              const float* __restrict__ phase_b,
              const float* __restrict__ alpha_p, const float* __restrict__ beta_p,
              float* __restrict__ out)
{
    extern __shared__ char smem[];
    __half*  sPh  = (__half*)smem;
    __half*  sSa  = (__half*)(smem + 33280);
    float2*  redA = (float2*)(smem + 66560);
    float2*  redB = (float2*)(smem + 70656);

    const int tid  = threadIdx.x;
    const int b    = blockIdx.x;
    const int lane = tid & 31;
    const int wrp  = tid >> 5;
    const int sb   = wrp >> 2;        // src block 0..3
    const int db   = wrp & 3;         // dst block 0..3
    const int d    = db * 32 + lane;  // dst for partials
    const int dp   = sb * 32 + lane;  // state owner index
    const int lp   = lane & 15;       // pair index this lane packs

    // ---- recurrent params into registers: src pairs [16*sb .. 16*sb+16) x dst d
    __half2 rp1[16], rc[16], rw[16], rwab[16];
    #pragma unroll
    for (int i = 0; i < 16; ++i) {
        int e = (sb * 16 + i) * Hdim + d;
        rp1[i]  = g_RP1h[e];
        rc[i]   = g_RCh[e];
        rw[i]   = g_RWh[e];
        rwab[i] = __habs2(rw[i]);
    }

    // ---- epilogue weights into padded smem rows (pitch 130 halfs)
    {
        const __half2* ph2 = (const __half2*)g_Ph;
        const __half2* sa2 = (const __half2*)g_Sa;
        #pragma unroll 2
        for (int i = tid; i < (Hdim*Hdim)/2; i += 512) {
            int dd = i >> 6, jj = i & 63;
            ((__half2*)((char*)sPh + dd * (PH_PITCH*2)))[jj] = ph2[i];
            ((__half2*)((char*)sSa + dd * (PH_PITCH*2)))[jj] = sa2[i];
        }
    }

    const float alpha = *alpha_p;
    const float beta  = *beta_p;

    // per-dp constants (state-owner side)
    const float KN   = g_KN[dp];
    const float KD   = g_KD[dp];
    const float cmt  = g_CmT[dp];
    const float aamp = alpha * amplitude[dp];
    const float omg  = omega[dp];
    const float phb  = phase_b[dp];
    float vreg = h0[b * Hdim + dp];        // v[dp], redundant across db

    // epilogue weight rows for dst d, k block sb (16 half2)
    const __half2* prow = (const __half2*)(sPh + d * PH_PITCH) + sb * 16;
    const __half2* srow = (const __half2*)(sSa + d * PH_PITCH) + sb * 16;

    const float2* senp = g_Sen + (size_t)(b * Sdim) * Hdim + dp;
    float2 sen = *senp;                     // prefetch t=0
    __syncthreads();                        // epilogue weights ready

    #pragma unroll 1
    for (int t = 0; t < Sdim; ++t) {
        const float N0 = KN + sen.x;
        const float D0 = KD + sen.y;
        if (t + 1 < Sdim) sen = senp[(t + 1) * Hdim];   // prefetch next step

        // ---- 5 fast unfolds: shuffle-fed f16x2, ONE barrier each
        #pragma unroll 1
        for (int u = 0; u < UNF - 1; ++u) {
            // pack pair lp: (v[32sb+2lp], v[32sb+2lp+1]) as half2
            float ve = __shfl_sync(FULLMASK, vreg, 2 * lp);
            float vo = __shfl_sync(FULLMASK, vreg, 2 * lp + 1);
            __half2 vh2 = __floats2half2_rn(ve, vo);
            uint32_t vh2u = *reinterpret_cast<uint32_t*>(&vh2);

            __half2 qn2 = __floats2half2_rn(0.f, 0.f);
            __half2 qd2 = qn2;
            #pragma unroll
            for (int i = 0; i < 16; ++i) {
                uint32_t vu = __shfl_sync(FULLMASK, vh2u, i);
                __half2 vh = *reinterpret_cast<__half2*>(&vu);
                __half2 arg = __hfma2(rp1[i], vh, rc[i]);
                __half2 th  = ltc_tanh_h2(arg);
                qn2 = __hfma2(rw[i],   th, qn2);
                qd2 = __hfma2(rwab[i], th, qd2);
            }
            float2 qnf = __half22float2(qn2);
            float2 qdf = __half22float2(qd2);
            float2* red = (u & 1) ? redB : redA;
            red[tid] = make_float2(qnf.x + qnf.y, qdf.x + qdf.y);
            __syncthreads();
            float2 r0 = red[dp], r1 = red[dp+128], r2 = red[dp+256], r3 = red[dp+384];
            float num = fmaf(cmt, vreg, N0 + r0.x + r1.x + r2.x + r3.x);
            float den = D0 + r0.y + r1.y + r2.y + r3.y;
            vreg = __fdividef(num, den);    // all threads, redundant x4
        }

        // ---- final unfold: accurate fp32 (parity: u=5 -> redB)
        {
            float qn = 0.f, qd = 0.f;
            #pragma unroll
            for (int i = 0; i < 16; ++i) {
                float v0 = __shfl_sync(FULLMASK, vreg, 2 * i);
                float v1 = __shfl_sync(FULLMASK, vreg, 2 * i + 1);
                float2 a  = __half22float2(rp1[i]);
                float2 c  = __half22float2(rc[i]);
                float2 wf = __half22float2(rw[i]);
                float th0 = ltc_tanh_f32(fmaf(a.x, v0, c.x));
                float th1 = ltc_tanh_f32(fmaf(a.y, v1, c.y));
                qn = fmaf(wf.x, th0, qn);
                qn = fmaf(wf.y, th1, qn);
                qd = fmaf(fabsf(wf.x), th0, qd);
                qd = fmaf(fabsf(wf.y), th1, qd);
            }
            redB[tid] = make_float2(qn, qd);
            __syncthreads();
            float2 r0 = redB[dp], r1 = redB[dp+128], r2 = redB[dp+256], r3 = redB[dp+384];
            float num = fmaf(cmt, vreg, N0 + r0.x + r1.x + r2.x + r3.x);
            float den = D0 + r0.y + r1.y + r2.y + r3.y;
            vreg = __fdividef(num, den);
        }

        // ---- pulse: phi[d] = sum_k Ph[d][k] v[k]; k block sb via shuffles (redA)
        {
            float ph = 0.f;
            #pragma unroll
            for (int j = 0; j < 16; ++j) {
                float2 wf = __half22float2(prow[j]);
                float vk0 = __shfl_sync(FULLMASK, vreg, 2 * j);
                float vk1 = __shfl_sync(FULLMASK, vreg, 2 * j + 1);
                ph = fmaf(wf.x, vk0, ph);
                ph = fmaf(wf.y, vk1, ph);
            }
            float* redf = (float*)redA;
            redf[tid] = ph;
            __syncthreads();
            float phi = redf[dp] + redf[dp+128] + redf[dp+256] + redf[dp+384] + phb;
            vreg = fmaf(aamp, __sinf(fmaf(omg, (float)t, phi)), vreg);
        }

        // ---- self-attend: v += beta * (sigmoid(v) @ sa_W^T)  (redB)
        {
            float sgv = 0.5f + 0.5f * ltc_tanh_f32(0.5f * vreg);   // sigmoid(v[dp])
            float sa = 0.f;
            #pragma unroll
            for (int j = 0; j < 16; ++j) {
                float2 wf = __half22float2(srow[j]);
                float s0 = __shfl_sync(FULLMASK, sgv, 2 * j);
                float s1 = __shfl_sync(FULLMASK, sgv, 2 * j + 1);
                sa = fmaf(wf.x, s0, sa);
                sa = fmaf(wf.y, s1, sa);
            }
            float* redf = (float*)redB;
            redf[tid] = sa;
            __syncthreads();
            vreg = fmaf(beta, redf[dp] + redf[dp+128] + redf[dp+256] + redf[dp+384], vreg);
        }

        if (db == 0)
            out[(size_t)(b * Sdim + t) * Hdim + dp] = vreg;
    }

    if (db == 0)
        out[(size_t)Bdim * Sdim * Hdim + b * Hdim + dp] = vreg;
}

// ---------------- launch ----------------
extern "C" void kernel_launch(void* const* d_in, const int* in_sizes, int n_in,
                              void* d_out, int out_size)
{
    const float* x        = (const float*)d_in[0];
    const float* h0       = (const float*)d_in[1];
    const float* input_w  = (const float*)d_in[2];
    const float* input_b  = (const float*)d_in[3];
    const float* gleak    = (const float*)d_in[4];
    const float* vleak    = (const float*)d_in[5];
    const float* cm       = (const float*)d_in[6];
    const float* sigma    = (const float*)d_in[7];
    const float* mu       = (const float*)d_in[8];
    const float* w        = (const float*)d_in[9];
    const float* erev     = (const float*)d_in[10];
    const float* s_sigma  = (const float*)d_in[11];
    const float* s_mu     = (const float*)d_in[12];
    const float* s_w      = (const float*)d_in[13];
    const float* s_erev   = (const float*)d_in[14];
    const float* amplitude= (const float*)d_in[15];
    const float* omega    = (const float*)d_in[16];
    const float* phase_W  = (const float*)d_in[17];
    const float* phase_b  = (const float*)d_in[18];
    const float* alpha    = (const float*)d_in[19];
    const float* sa_W     = (const float*)d_in[20];
    const float* beta     = (const float*)d_in[21];
    float* out = (float*)d_out;

    ltc_pre1<<<64, 256>>>(sigma, mu, w, erev, s_sigma, s_mu, s_w, s_erev,
                          input_w, input_b, phase_W, sa_W);
    ltc_pre2<<<1, 128>>>(gleak, vleak, cm, w, erev, s_w, s_erev);

    cudaFuncSetAttribute(ltc_sensory, cudaFuncAttributeMaxDynamicSharedMemorySize, SEN_SMEM);
    ltc_sensory<<<148, 256, SEN_SMEM>>>(x);

    cudaFuncSetAttribute(ltc_scan, cudaFuncAttributeMaxDynamicSharedMemorySize, SCAN_SMEM);
    ltc_scan<<<Bdim, 512, SCAN_SMEM>>>(h0, amplitude, omega, phase_b,
                                       alpha, beta, out);
}

// round 11
// speedup vs baseline: 1.1758x; 1.1758x over previous
#include <cuda_runtime.h>
#include <cuda_fp16.h>
#include <math.h>
#include <stdint.h>

#define Bdim 64
#define Sdim 256
#define Idim 128
#define Hdim 128
#define UNF  6
#define UNF_FAST 4            // 4 fast f16x2 unfolds + 1 accurate fp32 unfold
#define EPSV 1e-8f

// ---------------- device scratch ----------------
// pair-packed recurrent params: index e = p*128 + d, p = src/2 (0..63)
__device__ __half2 g_RP1h[64*Hdim];  // (0.5*sigma[2p,d], 0.5*sigma[2p+1,d])
__device__ __half2 g_RCh [64*Hdim];  // (-0.5*sigma*mu) pairs
__device__ __half2 g_RWh [64*Hdim];  // (0.5*softplus(w)*erev) pairs
// pair-packed sensory params (fp16)
__device__ __half2 g_SP1[64*Hdim];
__device__ __half2 g_SC [64*Hdim];
__device__ __half2 g_SW [64*Hdim];
// epilogue matvec weights, [d][k] row-major fp16
__device__ __half  g_Ph[Hdim*Hdim];
__device__ __half  g_Sa[Hdim*Hdim];
__device__ float   g_KN[Hdim];
__device__ float   g_KD[Hdim];
__device__ float   g_CmT[Hdim];
__device__ float2  g_Sen[Bdim*Sdim*Hdim];   // per-(b,t,d): (num_s, den_s)

static __device__ __forceinline__ float ltc_softplus(float x) {
    return fmaxf(x, 0.f) + log1pf(expf(-fabsf(x)));
}
static __device__ __forceinline__ float ltc_tanh_f32(float x) {
    float y; asm("tanh.approx.f32 %0, %1;" : "=f"(y) : "f"(x)); return y;
}
static __device__ __forceinline__ __half2 ltc_tanh_h2(__half2 x) {
    uint32_t xi = *reinterpret_cast<uint32_t*>(&x);
    uint32_t yi;
    asm("tanh.approx.f16x2 %0, %1;" : "=r"(yi) : "r"(xi));
    return *reinterpret_cast<__half2*>(&yi);
}

// ---------------- precompute ----------------
__global__ void ltc_pre1(const float* __restrict__ sigma, const float* __restrict__ mu,
                         const float* __restrict__ w,     const float* __restrict__ erev,
                         const float* __restrict__ s_sigma, const float* __restrict__ s_mu,
                         const float* __restrict__ s_w,   const float* __restrict__ s_erev,
                         const float* __restrict__ input_w, const float* __restrict__ input_b,
                         const float* __restrict__ phase_W, const float* __restrict__ sa_W)
{
    int e = blockIdx.x * blockDim.x + threadIdx.x;
    if (e >= Hdim * Hdim) return;
    g_Ph[e] = __float2half(phase_W[e]);
    g_Sa[e] = __float2half(sa_W[e]);

    if (e < 64 * Hdim) {
        int p = e >> 7, d = e & 127;
        int s0 = 2 * p, s1 = 2 * p + 1;
        float sg0 = sigma[s0*Hdim+d], sg1 = sigma[s1*Hdim+d];
        g_RP1h[e] = __floats2half2_rn(0.5f*sg0, 0.5f*sg1);
        g_RCh [e] = __floats2half2_rn(-0.5f*sg0*mu[s0*Hdim+d], -0.5f*sg1*mu[s1*Hdim+d]);
        g_RWh [e] = __floats2half2_rn(0.5f*ltc_softplus(w[s0*Hdim+d])*erev[s0*Hdim+d],
                                      0.5f*ltc_softplus(w[s1*Hdim+d])*erev[s1*Hdim+d]);
        float ss0 = s_sigma[s0*Hdim+d], ss1 = s_sigma[s1*Hdim+d];
        g_SP1[e] = __floats2half2_rn(0.5f*ss0*input_w[s0], 0.5f*ss1*input_w[s1]);
        g_SC [e] = __floats2half2_rn(0.5f*ss0*(input_b[s0]-s_mu[s0*Hdim+d]),
                                     0.5f*ss1*(input_b[s1]-s_mu[s1*Hdim+d]));
        g_SW [e] = __floats2half2_rn(0.5f*ltc_softplus(s_w[s0*Hdim+d])*s_erev[s0*Hdim+d],
                                     0.5f*ltc_softplus(s_w[s1*Hdim+d])*s_erev[s1*Hdim+d]);
    }
}

__global__ void ltc_pre2(const float* __restrict__ gleak, const float* __restrict__ vleak,
                         const float* __restrict__ cm,
                         const float* __restrict__ w, const float* __restrict__ erev,
                         const float* __restrict__ s_w, const float* __restrict__ s_erev)
{
    int d = threadIdx.x;
    if (d >= Hdim) return;
    float Cn = 0.f, Cd = 0.f;
    for (int s = 0; s < Hdim; ++s) {
        float v = 0.5f * ltc_softplus(w[s*Hdim+d]) * erev[s*Hdim+d];
        Cn += v; Cd += fabsf(v);
    }
    for (int i = 0; i < Idim; ++i) {
        float v = 0.5f * ltc_softplus(s_w[i*Hdim+d]) * s_erev[i*Hdim+d];
        Cn += v; Cd += fabsf(v);
    }
    float gl  = ltc_softplus(gleak[d]);
    float cmt = ltc_softplus(cm[d]) * ((float)UNF / 1.0f);
    g_KN[d]  = gl * vleak[d] + Cn;
    g_KD[d]  = cmt + gl + Cd + EPSV;
    g_CmT[d] = cmt;
}

// ---------------- sensory precompute (parallel over all (b,t)) ----------------
#define SEN_SMEM 100608

__global__ __launch_bounds__(256, 1)
void ltc_sensory(const float* __restrict__ x)
{
    extern __shared__ char smem[];
    __half2* sP1 = (__half2*)smem;
    __half2* sC  = (__half2*)(smem + 32768);
    __half2* sW  = (__half2*)(smem + 65536);
    __half2* sxh = (__half2*)(smem + 98304);
    float*   red = (float*)(smem + 98560);

    const int tid = threadIdx.x;
    for (int i = tid; i < 64*Hdim; i += 256) {
        sP1[i] = g_SP1[i]; sC[i] = g_SC[i]; sW[i] = g_SW[i];
    }
    __syncthreads();

    const int d  = tid & 127;
    const int p0 = (tid >> 7) * 32;

    for (int item = blockIdx.x; item < Bdim*Sdim; item += gridDim.x) {
        if (tid < 64) {
            float2 x2 = ((const float2*)(x + (size_t)item * Idim))[tid];
            sxh[tid] = __floats2half2_rn(x2.x, x2.y);
        }
        __syncthreads();
        float qn = 0.f, qd = 0.f;
        #pragma unroll
        for (int i = 0; i < 32; ++i) {
            int e = (p0 + i) * Hdim + d;
            __half2 arg = __hfma2(sP1[e], sxh[p0 + i], sC[e]);
            float2 th = __half22float2(ltc_tanh_h2(arg));
            float2 wf = __half22float2(sW[e]);
            qn = fmaf(wf.x, th.x, qn); qn = fmaf(wf.y, th.y, qn);
            qd = fmaf(fabsf(wf.x), th.x, qd); qd = fmaf(fabsf(wf.y), th.y, qd);
        }
        red[tid] = qn;
        red[256 + tid] = qd;
        __syncthreads();
        if (tid < 128)
            g_Sen[(size_t)item * Hdim + tid] = make_float2(red[tid] + red[tid + 128],
                                                           red[256 + tid] + red[384 + tid]);
        __syncthreads();
    }
}

// ---------------- scan kernel: 1 CTA/batch, 512 threads -----------------------
// d = tid & 127, q = tid >> 7 (src quarter; warp-uniform)
// smem:
//   0      sPh  half [128 rows, pitch 130] 33280
//   33280  sSa  half [128 rows, pitch 130] 33280 -> 66560
//   66560  svF  float[128]   512 -> 67072   (fp32 state)
//   67072  sgs  float[128]   512 -> 67584
//   67584  svH  half[128]    256 -> 67840   (fp16 state for fast unfolds)
//   67840  red2 float2[512] 4096 -> 71936   (aliased as float[1024] in epilogue)
#define SCAN_SMEM 71936
#define PH_PITCH 130

__global__ __launch_bounds__(512, 1)
void ltc_scan(const float* __restrict__ h0,
              const float* __restrict__ amplitude, const float* __restrict__ omega,
              const float* __restrict__ phase_b,
              const float* __restrict__ alpha_p, const float* __restrict__ beta_p,
              float* __restrict__ out)
{
    extern __shared__ char smem[];
    __half*  sPh  = (__half*)smem;
    __half*  sSa  = (__half*)(smem + 33280);
    float*   svF  = (float*)(smem + 66560);
    float*   sgs  = (float*)(smem + 67072);
    __half2* svH2 = (__half2*)(smem + 67584);   // 64 half2
    float2*  red2 = (float2*)(smem + 67840);
    float*   redf = (float*)(smem + 67840);     // alias (epilogue)

    const int tid = threadIdx.x;
    const int b   = blockIdx.x;
    const int d   = tid & 127;       // dst
    const int q   = tid >> 7;        // src quarter (warp-uniform)
    const int p0  = q * 16;          // first src pair

    // ---- recurrent params into registers (half2)
    __half2 rp1[16], rc[16], rw[16], rwab[16];
    #pragma unroll
    for (int i = 0; i < 16; ++i) {
        int e = (p0 + i) * Hdim + d;
        rp1[i]  = g_RP1h[e];
        rc[i]   = g_RCh[e];
        rw[i]   = g_RWh[e];
        rwab[i] = __habs2(rw[i]);
    }

    // ---- epilogue weights into padded smem rows (pitch 130 halfs)
    {
        const __half2* ph2 = (const __half2*)g_Ph;
        const __half2* sa2 = (const __half2*)g_Sa;
        #pragma unroll 2
        for (int i = tid; i < (Hdim*Hdim)/2; i += 512) {
            int dd = i >> 6, jj = i & 63;
            ((__half2*)((char*)sPh + dd * (PH_PITCH*2)))[jj] = ph2[i];
            ((__half2*)((char*)sSa + dd * (PH_PITCH*2)))[jj] = sa2[i];
        }
    }
    if (tid < 128) {
        float v = h0[b * Hdim + tid];
        svF[tid] = v;
        ((__half*)svH2)[tid] = __float2half(v);
    }
    __syncthreads();

    const float alpha = *alpha_p;
    const float beta  = *beta_p;

    const float KN   = g_KN[d];
    const float KD   = g_KD[d];
    const float cmt  = g_CmT[d];
    const float aamp = alpha * amplitude[d];
    const float omg  = omega[d];
    const float phb  = phase_b[d];
    float vreg = svF[d];             // writer lanes keep the running state

    const int kh0 = q * 16;          // epilogue k quarter (in float2/half2 units)

    #pragma unroll 1
    for (int t = 0; t < Sdim; ++t) {
        float2 sen = g_Sen[(size_t)(b * Sdim + t) * Hdim + d];
        float N0 = KN + sen.x;
        float D0 = KD + sen.y;

        // ---- 4 fast unfolds: all-f16x2 inner loop, h2 accumulators
        #pragma unroll 1
        for (int u = 0; u < UNF_FAST; ++u) {
            __half2 qn2 = __floats2half2_rn(0.f, 0.f);
            __half2 qd2 = qn2;
            #pragma unroll
            for (int i = 0; i < 16; ++i) {
                __half2 vh  = svH2[p0 + i];                 // bcast LDS.32
                __half2 arg = __hfma2(rp1[i], vh, rc[i]);
                __half2 th  = ltc_tanh_h2(arg);
                qn2 = __hfma2(rw[i],   th, qn2);
                qd2 = __hfma2(rwab[i], th, qd2);
            }
            float2 qnf = __half22float2(qn2);
            float2 qdf = __half22float2(qd2);
            red2[tid] = make_float2(qnf.x + qnf.y, qdf.x + qdf.y);
            __syncthreads();
            if (tid < 128) {
                float2 r0 = red2[d], r1 = red2[d+128], r2 = red2[d+256], r3 = red2[d+384];
                float num = fmaf(cmt, vreg, N0 + r0.x + r1.x + r2.x + r3.x);
                float den = D0 + r0.y + r1.y + r2.y + r3.y;
                vreg = __fdividef(num, den);
                ((__half*)svH2)[d] = __float2half(vreg);
                if (u == UNF_FAST - 1) svF[d] = vreg;  // fp32 input for accurate unfold
            }
            __syncthreads();
        }

        // ---- final unfold: accurate fp32 args + tanh.f32 (reads svF)
        {
            const float2* sv2 = (const float2*)svF;
            float qn = 0.f, qd = 0.f;
            #pragma unroll
            for (int i = 0; i < 16; ++i) {
                float2 v2 = sv2[p0 + i];
                float2 a  = __half22float2(rp1[i]);
                float2 c  = __half22float2(rc[i]);
                float2 wf = __half22float2(rw[i]);
                float th0 = ltc_tanh_f32(fmaf(a.x, v2.x, c.x));
                float th1 = ltc_tanh_f32(fmaf(a.y, v2.y, c.y));
                qn = fmaf(wf.x, th0, qn);
                qn = fmaf(wf.y, th1, qn);
                qd = fmaf(fabsf(wf.x), th0, qd);
                qd = fmaf(fabsf(wf.y), th1, qd);
            }
            red2[tid] = make_float2(qn, qd);
            __syncthreads();
            if (tid < 128) {
                float2 r0 = red2[d], r1 = red2[d+128], r2 = red2[d+256], r3 = red2[d+384];
                float num = fmaf(cmt, vreg, N0 + r0.x + r1.x + r2.x + r3.x);
                float den = D0 + r0.y + r1.y + r2.y + r3.y;
                vreg = __fdividef(num, den);
                svF[d] = vreg;
                // sigmoid of PRE-pulse v for fused self-attend (error ~6e-6)
                sgs[d] = 0.5f + 0.5f * ltc_tanh_f32(0.5f * vreg);
            }
            __syncthreads();
        }

        // ---- FUSED epilogue: pulse matvec + self-attend matvec in one phase
        {
            float ph = 0.f, sa = 0.f;
            const __half2* prow = (const __half2*)(sPh + d * PH_PITCH) + kh0;
            const __half2* srow = (const __half2*)(sSa + d * PH_PITCH) + kh0;
            const float2* sv2 = (const float2*)svF + kh0;
            const float2* sg2 = (const float2*)sgs + kh0;
            #pragma unroll
            for (int j = 0; j < 16; ++j) {
                float2 wp = __half22float2(prow[j]);
                float2 ws = __half22float2(srow[j]);
                float2 v2 = sv2[j];
                float2 s2 = sg2[j];
                ph = fmaf(wp.x, v2.x, ph);
                ph = fmaf(wp.y, v2.y, ph);
                sa = fmaf(ws.x, s2.x, sa);
                sa = fmaf(ws.y, s2.y, sa);
            }
            redf[tid] = ph;
            redf[512 + tid] = sa;
        }
        __syncthreads();
        if (tid < 128) {
            float phi = redf[d] + redf[d+128] + redf[d+256] + redf[d+384] + phb;
            float sas = redf[512+d] + redf[512+d+128] + redf[512+d+256] + redf[512+d+384];
            vreg = fmaf(aamp, __sinf(fmaf(omg, (float)t, phi)), vreg);
            vreg = fmaf(beta, sas, vreg);
            svF[d] = vreg;
            ((__half*)svH2)[d] = __float2half(vreg);   // state for next step
            out[(size_t)(b * Sdim + t) * Hdim + d] = vreg;
        }
        __syncthreads();
    }

    if (tid < 128)
        out[(size_t)Bdim * Sdim * Hdim + b * Hdim + d] = vreg;
}

// ---------------- launch ----------------
extern "C" void kernel_launch(void* const* d_in, const int* in_sizes, int n_in,
                              void* d_out, int out_size)
{
    const float* x        = (const float*)d_in[0];
    const float* h0       = (const float*)d_in[1];
    const float* input_w  = (const float*)d_in[2];
    const float* input_b  = (const float*)d_in[3];
    const float* gleak    = (const float*)d_in[4];
    const float* vleak    = (const float*)d_in[5];
    const float* cm       = (const float*)d_in[6];
    const float* sigma    = (const float*)d_in[7];
    const float* mu       = (const float*)d_in[8];
    const float* w        = (const float*)d_in[9];
    const float* erev     = (const float*)d_in[10];
    const float* s_sigma  = (const float*)d_in[11];
    const float* s_mu     = (const float*)d_in[12];
    const float* s_w      = (const float*)d_in[13];
    const float* s_erev   = (const float*)d_in[14];
    const float* amplitude= (const float*)d_in[15];
    const float* omega    = (const float*)d_in[16];
    const float* phase_W  = (const float*)d_in[17];
    const float* phase_b  = (const float*)d_in[18];
    const float* alpha    = (const float*)d_in[19];
    const float* sa_W     = (const float*)d_in[20];
    const float* beta     = (const float*)d_in[21];
    float* out = (float*)d_out;

    ltc_pre1<<<64, 256>>>(sigma, mu, w, erev, s_sigma, s_mu, s_w, s_erev,
                          input_w, input_b, phase_W, sa_W);
    ltc_pre2<<<1, 128>>>(gleak, vleak, cm, w, erev, s_w, s_erev);

    cudaFuncSetAttribute(ltc_sensory, cudaFuncAttributeMaxDynamicSharedMemorySize, SEN_SMEM);
    ltc_sensory<<<148, 256, SEN_SMEM>>>(x);

    cudaFuncSetAttribute(ltc_scan, cudaFuncAttributeMaxDynamicSharedMemorySize, SCAN_SMEM);
    ltc_scan<<<Bdim, 512, SCAN_SMEM>>>(h0, amplitude, omega, phase_b,
                                       alpha, beta, out);
}

// round 12
// speedup vs baseline: 1.1765x; 1.0006x over previous
#include <cuda_runtime.h>
#include <cuda_fp16.h>
#include <math.h>
#include <stdint.h>

#define Bdim 64
#define Sdim 256
#define Idim 128
#define Hdim 128
#define UNF  6
#define UNF_FAST 4            // 4 fast f16x2 unfolds + 1 accurate fp32 unfold
#define EPSV 1e-8f

// ---------------- device scratch ----------------
// pair-packed recurrent params: index e = p*128 + d, p = src/2 (0..63)
__device__ __half2 g_RP1h[64*Hdim];  // (0.5*sigma[2p,d], 0.5*sigma[2p+1,d])
__device__ __half2 g_RCh [64*Hdim];  // (-0.5*sigma*mu) pairs
__device__ __half2 g_RWh [64*Hdim];  // (0.5*softplus(w)*erev) pairs
// pair-packed sensory params (fp16)
__device__ __half2 g_SP1[64*Hdim];
__device__ __half2 g_SC [64*Hdim];
__device__ __half2 g_SW [64*Hdim];
// epilogue matvec weights, [d][k] row-major fp16
__device__ __half  g_Ph[Hdim*Hdim];
__device__ __half  g_Sa[Hdim*Hdim];
__device__ float   g_KN[Hdim];
__device__ float   g_KD[Hdim];
__device__ float   g_CmT[Hdim];
__device__ float2  g_Sen[Bdim*Sdim*Hdim];   // per-(b,t,d): (num_s, den_s)

static __device__ __forceinline__ float ltc_softplus(float x) {
    return fmaxf(x, 0.f) + log1pf(expf(-fabsf(x)));
}
static __device__ __forceinline__ float ltc_tanh_f32(float x) {
    float y; asm("tanh.approx.f32 %0, %1;" : "=f"(y) : "f"(x)); return y;
}
static __device__ __forceinline__ __half2 ltc_tanh_h2(__half2 x) {
    uint32_t xi = *reinterpret_cast<uint32_t*>(&x);
    uint32_t yi;
    asm("tanh.approx.f16x2 %0, %1;" : "=r"(yi) : "r"(xi));
    return *reinterpret_cast<__half2*>(&yi);
}

// ---------------- precompute ----------------
__global__ void ltc_pre1(const float* __restrict__ sigma, const float* __restrict__ mu,
                         const float* __restrict__ w,     const float* __restrict__ erev,
                         const float* __restrict__ s_sigma, const float* __restrict__ s_mu,
                         const float* __restrict__ s_w,   const float* __restrict__ s_erev,
                         const float* __restrict__ input_w, const float* __restrict__ input_b,
                         const float* __restrict__ phase_W, const float* __restrict__ sa_W)
{
    int e = blockIdx.x * blockDim.x + threadIdx.x;
    if (e >= Hdim * Hdim) return;
    g_Ph[e] = __float2half(phase_W[e]);
    g_Sa[e] = __float2half(sa_W[e]);

    if (e < 64 * Hdim) {
        int p = e >> 7, d = e & 127;
        int s0 = 2 * p, s1 = 2 * p + 1;
        float sg0 = sigma[s0*Hdim+d], sg1 = sigma[s1*Hdim+d];
        g_RP1h[e] = __floats2half2_rn(0.5f*sg0, 0.5f*sg1);
        g_RCh [e] = __floats2half2_rn(-0.5f*sg0*mu[s0*Hdim+d], -0.5f*sg1*mu[s1*Hdim+d]);
        g_RWh [e] = __floats2half2_rn(0.5f*ltc_softplus(w[s0*Hdim+d])*erev[s0*Hdim+d],
                                      0.5f*ltc_softplus(w[s1*Hdim+d])*erev[s1*Hdim+d]);
        float ss0 = s_sigma[s0*Hdim+d], ss1 = s_sigma[s1*Hdim+d];
        g_SP1[e] = __floats2half2_rn(0.5f*ss0*input_w[s0], 0.5f*ss1*input_w[s1]);
        g_SC [e] = __floats2half2_rn(0.5f*ss0*(input_b[s0]-s_mu[s0*Hdim+d]),
                                     0.5f*ss1*(input_b[s1]-s_mu[s1*Hdim+d]));
        g_SW [e] = __floats2half2_rn(0.5f*ltc_softplus(s_w[s0*Hdim+d])*s_erev[s0*Hdim+d],
                                     0.5f*ltc_softplus(s_w[s1*Hdim+d])*s_erev[s1*Hdim+d]);
    }
}

__global__ void ltc_pre2(const float* __restrict__ gleak, const float* __restrict__ vleak,
                         const float* __restrict__ cm,
                         const float* __restrict__ w, const float* __restrict__ erev,
                         const float* __restrict__ s_w, const float* __restrict__ s_erev)
{
    int d = threadIdx.x;
    if (d >= Hdim) return;
    float Cn = 0.f, Cd = 0.f;
    for (int s = 0; s < Hdim; ++s) {
        float v = 0.5f * ltc_softplus(w[s*Hdim+d]) * erev[s*Hdim+d];
        Cn += v; Cd += fabsf(v);
    }
    for (int i = 0; i < Idim; ++i) {
        float v = 0.5f * ltc_softplus(s_w[i*Hdim+d]) * s_erev[i*Hdim+d];
        Cn += v; Cd += fabsf(v);
    }
    float gl  = ltc_softplus(gleak[d]);
    float cmt = ltc_softplus(cm[d]) * ((float)UNF / 1.0f);
    g_KN[d]  = gl * vleak[d] + Cn;
    g_KD[d]  = cmt + gl + Cd + EPSV;
    g_CmT[d] = cmt;
}

// ---------------- sensory precompute (parallel over all (b,t)) ----------------
#define SEN_SMEM 100608

__global__ __launch_bounds__(256, 1)
void ltc_sensory(const float* __restrict__ x)
{
    extern __shared__ char smem[];
    __half2* sP1 = (__half2*)smem;
    __half2* sC  = (__half2*)(smem + 32768);
    __half2* sW  = (__half2*)(smem + 65536);
    __half2* sxh = (__half2*)(smem + 98304);
    float*   red = (float*)(smem + 98560);

    const int tid = threadIdx.x;
    for (int i = tid; i < 64*Hdim; i += 256) {
        sP1[i] = g_SP1[i]; sC[i] = g_SC[i]; sW[i] = g_SW[i];
    }
    __syncthreads();

    const int d  = tid & 127;
    const int p0 = (tid >> 7) * 32;

    for (int item = blockIdx.x; item < Bdim*Sdim; item += gridDim.x) {
        if (tid < 64) {
            float2 x2 = ((const float2*)(x + (size_t)item * Idim))[tid];
            sxh[tid] = __floats2half2_rn(x2.x, x2.y);
        }
        __syncthreads();
        float qn = 0.f, qd = 0.f;
        #pragma unroll
        for (int i = 0; i < 32; ++i) {
            int e = (p0 + i) * Hdim + d;
            __half2 arg = __hfma2(sP1[e], sxh[p0 + i], sC[e]);
            float2 th = __half22float2(ltc_tanh_h2(arg));
            float2 wf = __half22float2(sW[e]);
            qn = fmaf(wf.x, th.x, qn); qn = fmaf(wf.y, th.y, qn);
            qd = fmaf(fabsf(wf.x), th.x, qd); qd = fmaf(fabsf(wf.y), th.y, qd);
        }
        red[tid] = qn;
        red[256 + tid] = qd;
        __syncthreads();
        if (tid < 128)
            g_Sen[(size_t)item * Hdim + tid] = make_float2(red[tid] + red[tid + 128],
                                                           red[256 + tid] + red[384 + tid]);
        __syncthreads();
    }
}

// ---------------- scan kernel: 1 CTA/batch, 512 threads -----------------------
// d = tid & 127, q = tid >> 7 (src quarter; warp-uniform)
// smem:
//   0      sPh  half [128 rows, pitch 130] 33280
//   33280  sSa  half [128 rows, pitch 130] 33280 -> 66560
//   66560  svF  float[128]   512 -> 67072   (fp32 state)
//   67072  sgs  float[128]   512 -> 67584
//   67584  svH  half[128]    256 -> 67840   (fp16 state for fast unfolds)
//   67840  red2 float2[512] 4096 -> 71936   (aliased as float[1024] in epilogue)
#define SCAN_SMEM 71936
#define PH_PITCH 130

__global__ __launch_bounds__(512, 1)
void ltc_scan(const float* __restrict__ h0,
              const float* __restrict__ amplitude, const float* __restrict__ omega,
              const float* __restrict__ phase_b,
              const float* __restrict__ alpha_p, const float* __restrict__ beta_p,
              float* __restrict__ out)
{
    extern __shared__ char smem[];
    __half*  sPh  = (__half*)smem;
    __half*  sSa  = (__half*)(smem + 33280);
    float*   svF  = (float*)(smem + 66560);
    float*   sgs  = (float*)(smem + 67072);
    __half2* svH2 = (__half2*)(smem + 67584);   // 64 half2
    float2*  red2 = (float2*)(smem + 67840);
    float*   redf = (float*)(smem + 67840);     // alias (epilogue)

    const int tid = threadIdx.x;
    const int b   = blockIdx.x;
    const int d   = tid & 127;       // dst
    const int q   = tid >> 7;        // src quarter (warp-uniform)
    const int p0  = q * 16;          // first src pair

    // ---- recurrent params into registers (half2)
    __half2 rp1[16], rc[16], rw[16], rwab[16];
    #pragma unroll
    for (int i = 0; i < 16; ++i) {
        int e = (p0 + i) * Hdim + d;
        rp1[i]  = g_RP1h[e];
        rc[i]   = g_RCh[e];
        rw[i]   = g_RWh[e];
        rwab[i] = __habs2(rw[i]);
    }

    // ---- epilogue weights into padded smem rows (pitch 130 halfs)
    {
        const __half2* ph2 = (const __half2*)g_Ph;
        const __half2* sa2 = (const __half2*)g_Sa;
        #pragma unroll 2
        for (int i = tid; i < (Hdim*Hdim)/2; i += 512) {
            int dd = i >> 6, jj = i & 63;
            ((__half2*)((char*)sPh + dd * (PH_PITCH*2)))[jj] = ph2[i];
            ((__half2*)((char*)sSa + dd * (PH_PITCH*2)))[jj] = sa2[i];
        }
    }
    if (tid < 128) {
        float v = h0[b * Hdim + tid];
        svF[tid] = v;
        ((__half*)svH2)[tid] = __float2half(v);
    }
    __syncthreads();

    const float alpha = *alpha_p;
    const float beta  = *beta_p;

    const float KN   = g_KN[d];
    const float KD   = g_KD[d];
    const float cmt  = g_CmT[d];
    const float aamp = alpha * amplitude[d];
    const float omg  = omega[d];
    const float phb  = phase_b[d];
    float vreg = svF[d];             // writer lanes keep the running state

    const int kh0 = q * 16;          // epilogue k quarter (in float2/half2 units)

    #pragma unroll 1
    for (int t = 0; t < Sdim; ++t) {
        float2 sen = g_Sen[(size_t)(b * Sdim + t) * Hdim + d];
        float N0 = KN + sen.x;
        float D0 = KD + sen.y;

        // ---- 4 fast unfolds: all-f16x2 inner loop, h2 accumulators
        #pragma unroll 1
        for (int u = 0; u < UNF_FAST; ++u) {
            __half2 qn2 = __floats2half2_rn(0.f, 0.f);
            __half2 qd2 = qn2;
            #pragma unroll
            for (int i = 0; i < 16; ++i) {
                __half2 vh  = svH2[p0 + i];                 // bcast LDS.32
                __half2 arg = __hfma2(rp1[i], vh, rc[i]);
                __half2 th  = ltc_tanh_h2(arg);
                qn2 = __hfma2(rw[i],   th, qn2);
                qd2 = __hfma2(rwab[i], th, qd2);
            }
            float2 qnf = __half22float2(qn2);
            float2 qdf = __half22float2(qd2);
            red2[tid] = make_float2(qnf.x + qnf.y, qdf.x + qdf.y);
            __syncthreads();
            if (tid < 128) {
                float2 r0 = red2[d], r1 = red2[d+128], r2 = red2[d+256], r3 = red2[d+384];
                float num = fmaf(cmt, vreg, N0 + r0.x + r1.x + r2.x + r3.x);
                float den = D0 + r0.y + r1.y + r2.y + r3.y;
                vreg = __fdividef(num, den);
                ((__half*)svH2)[d] = __float2half(vreg);
                if (u == UNF_FAST - 1) svF[d] = vreg;  // fp32 input for accurate unfold
            }
            __syncthreads();
        }

        // ---- final unfold: accurate fp32 args + tanh.f32 (reads svF)
        {
            const float2* sv2 = (const float2*)svF;
            float qn = 0.f, qd = 0.f;
            #pragma unroll
            for (int i = 0; i < 16; ++i) {
                float2 v2 = sv2[p0 + i];
                float2 a  = __half22float2(rp1[i]);
                float2 c  = __half22float2(rc[i]);
                float2 wf = __half22float2(rw[i]);
                float th0 = ltc_tanh_f32(fmaf(a.x, v2.x, c.x));
                float th1 = ltc_tanh_f32(fmaf(a.y, v2.y, c.y));
                qn = fmaf(wf.x, th0, qn);
                qn = fmaf(wf.y, th1, qn);
                qd = fmaf(fabsf(wf.x), th0, qd);
                qd = fmaf(fabsf(wf.y), th1, qd);
            }
            red2[tid] = make_float2(qn, qd);
            __syncthreads();
            if (tid < 128) {
                float2 r0 = red2[d], r1 = red2[d+128], r2 = red2[d+256], r3 = red2[d+384];
                float num = fmaf(cmt, vreg, N0 + r0.x + r1.x + r2.x + r3.x);
                float den = D0 + r0.y + r1.y + r2.y + r3.y;
                vreg = __fdividef(num, den);
                svF[d] = vreg;
                // sigmoid of PRE-pulse v for fused self-attend (error ~6e-6)
                sgs[d] = 0.5f + 0.5f * ltc_tanh_f32(0.5f * vreg);
            }
            __syncthreads();
        }

        // ---- FUSED epilogue: pulse matvec + self-attend matvec in one phase
        {
            float ph = 0.f, sa = 0.f;
            const __half2* prow = (const __half2*)(sPh + d * PH_PITCH) + kh0;
            const __half2* srow = (const __half2*)(sSa + d * PH_PITCH) + kh0;
            const float2* sv2 = (const float2*)svF + kh0;
            const float2* sg2 = (const float2*)sgs + kh0;
            #pragma unroll
            for (int j = 0; j < 16; ++j) {
                float2 wp = __half22float2(prow[j]);
                float2 ws = __half22float2(srow[j]);
                float2 v2 = sv2[j];
                float2 s2 = sg2[j];
                ph = fmaf(wp.x, v2.x, ph);
                ph = fmaf(wp.y, v2.y, ph);
                sa = fmaf(ws.x, s2.x, sa);
                sa = fmaf(ws.y, s2.y, sa);
            }
            redf[tid] = ph;
            redf[512 + tid] = sa;
        }
        __syncthreads();
        if (tid < 128) {
            float phi = redf[d] + redf[d+128] + redf[d+256] + redf[d+384] + phb;
            float sas = redf[512+d] + redf[512+d+128] + redf[512+d+256] + redf[512+d+384];
            vreg = fmaf(aamp, __sinf(fmaf(omg, (float)t, phi)), vreg);
            vreg = fmaf(beta, sas, vreg);
            svF[d] = vreg;
            ((__half*)svH2)[d] = __float2half(vreg);   // state for next step
            out[(size_t)(b * Sdim + t) * Hdim + d] = vreg;
        }
        __syncthreads();
    }

    if (tid < 128)
        out[(size_t)Bdim * Sdim * Hdim + b * Hdim + d] = vreg;
}

// ---------------- launch ----------------
extern "C" void kernel_launch(void* const* d_in, const int* in_sizes, int n_in,
                              void* d_out, int out_size)
{
    const float* x        = (const float*)d_in[0];
    const float* h0       = (const float*)d_in[1];
    const float* input_w  = (const float*)d_in[2];
    const float* input_b  = (const float*)d_in[3];
    const float* gleak    = (const float*)d_in[4];
    const float* vleak    = (const float*)d_in[5];
    const float* cm       = (const float*)d_in[6];
    const float* sigma    = (const float*)d_in[7];
    const float* mu       = (const float*)d_in[8];
    const float* w        = (const float*)d_in[9];
    const float* erev     = (const float*)d_in[10];
    const float* s_sigma  = (const float*)d_in[11];
    const float* s_mu     = (const float*)d_in[12];
    const float* s_w      = (const float*)d_in[13];
    const float* s_erev   = (const float*)d_in[14];
    const float* amplitude= (const float*)d_in[15];
    const float* omega    = (const float*)d_in[16];
    const float* phase_W  = (const float*)d_in[17];
    const float* phase_b  = (const float*)d_in[18];
    const float* alpha    = (const float*)d_in[19];
    const float* sa_W     = (const float*)d_in[20];
    const float* beta     = (const float*)d_in[21];
    float* out = (float*)d_out;

    ltc_pre1<<<64, 256>>>(sigma, mu, w, erev, s_sigma, s_mu, s_w, s_erev,
                          input_w, input_b, phase_W, sa_W);
    ltc_pre2<<<1, 128>>>(gleak, vleak, cm, w, erev, s_w, s_erev);

    cudaFuncSetAttribute(ltc_sensory, cudaFuncAttributeMaxDynamicSharedMemorySize, SEN_SMEM);
    ltc_sensory<<<148, 256, SEN_SMEM>>>(x);

    cudaFuncSetAttribute(ltc_scan, cudaFuncAttributeMaxDynamicSharedMemorySize, SCAN_SMEM);
    ltc_scan<<<Bdim, 512, SCAN_SMEM>>>(h0, amplitude, omega, phase_b,
                                       alpha, beta, out);
}

// round 13
// speedup vs baseline: 1.1768x; 1.0002x over previous
#include <cuda_runtime.h>
#include <cuda_fp16.h>
#include <math.h>
#include <stdint.h>

#define Bdim 64
#define Sdim 256
#define Idim 128
#define Hdim 128
#define UNF  6
#define UNF_FAST 4            // 4 fast f16x2 unfolds + 1 accurate fp32 unfold
#define EPSV 1e-8f

// ---------------- device scratch ----------------
// pair-packed recurrent params: index e = p*128 + d, p = src/2 (0..63)
__device__ __half2 g_RP1h[64*Hdim];  // (0.5*sigma[2p,d], 0.5*sigma[2p+1,d])
__device__ __half2 g_RCh [64*Hdim];  // (-0.5*sigma*mu) pairs
__device__ __half2 g_RWh [64*Hdim];  // (0.5*softplus(w)*erev) pairs
// pair-packed sensory params (fp16)
__device__ __half2 g_SP1[64*Hdim];
__device__ __half2 g_SC [64*Hdim];
__device__ __half2 g_SW [64*Hdim];
// epilogue matvec weights, [d][k] row-major fp16
__device__ __half  g_Ph[Hdim*Hdim];
__device__ __half  g_Sa[Hdim*Hdim];
__device__ float   g_KN[Hdim];
__device__ float   g_KD[Hdim];
__device__ float   g_CmT[Hdim];
__device__ float2  g_Sen[Bdim*Sdim*Hdim];   // per-(b,t,d): (num_s, den_s)

static __device__ __forceinline__ float ltc_softplus(float x) {
    return fmaxf(x, 0.f) + log1pf(expf(-fabsf(x)));
}
static __device__ __forceinline__ float ltc_tanh_f32(float x) {
    float y; asm("tanh.approx.f32 %0, %1;" : "=f"(y) : "f"(x)); return y;
}
static __device__ __forceinline__ __half2 ltc_tanh_h2(__half2 x) {
    uint32_t xi = *reinterpret_cast<uint32_t*>(&x);
    uint32_t yi;
    asm("tanh.approx.f16x2 %0, %1;" : "=r"(yi) : "r"(xi));
    return *reinterpret_cast<__half2*>(&yi);
}

// ---------------- precompute ----------------
__global__ void ltc_pre1(const float* __restrict__ sigma, const float* __restrict__ mu,
                         const float* __restrict__ w,     const float* __restrict__ erev,
                         const float* __restrict__ s_sigma, const float* __restrict__ s_mu,
                         const float* __restrict__ s_w,   const float* __restrict__ s_erev,
                         const float* __restrict__ input_w, const float* __restrict__ input_b,
                         const float* __restrict__ phase_W, const float* __restrict__ sa_W)
{
    int e = blockIdx.x * blockDim.x + threadIdx.x;
    if (e >= Hdim * Hdim) return;
    g_Ph[e] = __float2half(phase_W[e]);
    g_Sa[e] = __float2half(sa_W[e]);

    if (e < 64 * Hdim) {
        int p = e >> 7, d = e & 127;
        int s0 = 2 * p, s1 = 2 * p + 1;
        float sg0 = sigma[s0*Hdim+d], sg1 = sigma[s1*Hdim+d];
        g_RP1h[e] = __floats2half2_rn(0.5f*sg0, 0.5f*sg1);
        g_RCh [e] = __floats2half2_rn(-0.5f*sg0*mu[s0*Hdim+d], -0.5f*sg1*mu[s1*Hdim+d]);
        g_RWh [e] = __floats2half2_rn(0.5f*ltc_softplus(w[s0*Hdim+d])*erev[s0*Hdim+d],
                                      0.5f*ltc_softplus(w[s1*Hdim+d])*erev[s1*Hdim+d]);
        float ss0 = s_sigma[s0*Hdim+d], ss1 = s_sigma[s1*Hdim+d];
        g_SP1[e] = __floats2half2_rn(0.5f*ss0*input_w[s0], 0.5f*ss1*input_w[s1]);
        g_SC [e] = __floats2half2_rn(0.5f*ss0*(input_b[s0]-s_mu[s0*Hdim+d]),
                                     0.5f*ss1*(input_b[s1]-s_mu[s1*Hdim+d]));
        g_SW [e] = __floats2half2_rn(0.5f*ltc_softplus(s_w[s0*Hdim+d])*s_erev[s0*Hdim+d],
                                     0.5f*ltc_softplus(s_w[s1*Hdim+d])*s_erev[s1*Hdim+d]);
    }
}

__global__ void ltc_pre2(const float* __restrict__ gleak, const float* __restrict__ vleak,
                         const float* __restrict__ cm,
                         const float* __restrict__ w, const float* __restrict__ erev,
                         const float* __restrict__ s_w, const float* __restrict__ s_erev)
{
    int d = threadIdx.x;
    if (d >= Hdim) return;
    float Cn = 0.f, Cd = 0.f;
    for (int s = 0; s < Hdim; ++s) {
        float v = 0.5f * ltc_softplus(w[s*Hdim+d]) * erev[s*Hdim+d];
        Cn += v; Cd += fabsf(v);
    }
    for (int i = 0; i < Idim; ++i) {
        float v = 0.5f * ltc_softplus(s_w[i*Hdim+d]) * s_erev[i*Hdim+d];
        Cn += v; Cd += fabsf(v);
    }
    float gl  = ltc_softplus(gleak[d]);
    float cmt = ltc_softplus(cm[d]) * ((float)UNF / 1.0f);
    g_KN[d]  = gl * vleak[d] + Cn;
    g_KD[d]  = cmt + gl + Cd + EPSV;
    g_CmT[d] = cmt;
}

// ---------------- sensory precompute (parallel over all (b,t)) ----------------
#define SEN_SMEM 100608

__global__ __launch_bounds__(256, 1)
void ltc_sensory(const float* __restrict__ x)
{
    extern __shared__ char smem[];
    __half2* sP1 = (__half2*)smem;
    __half2* sC  = (__half2*)(smem + 32768);
    __half2* sW  = (__half2*)(smem + 65536);
    __half2* sxh = (__half2*)(smem + 98304);
    float*   red = (float*)(smem + 98560);

    const int tid = threadIdx.x;
    for (int i = tid; i < 64*Hdim; i += 256) {
        sP1[i] = g_SP1[i]; sC[i] = g_SC[i]; sW[i] = g_SW[i];
    }
    __syncthreads();

    const int d  = tid & 127;
    const int p0 = (tid >> 7) * 32;

    for (int item = blockIdx.x; item < Bdim*Sdim; item += gridDim.x) {
        if (tid < 64) {
            float2 x2 = ((const float2*)(x + (size_t)item * Idim))[tid];
            sxh[tid] = __floats2half2_rn(x2.x, x2.y);
        }
        __syncthreads();
        float qn = 0.f, qd = 0.f;
        #pragma unroll
        for (int i = 0; i < 32; ++i) {
            int e = (p0 + i) * Hdim + d;
            __half2 arg = __hfma2(sP1[e], sxh[p0 + i], sC[e]);
            float2 th = __half22float2(ltc_tanh_h2(arg));
            float2 wf = __half22float2(sW[e]);
            qn = fmaf(wf.x, th.x, qn); qn = fmaf(wf.y, th.y, qn);
            qd = fmaf(fabsf(wf.x), th.x, qd); qd = fmaf(fabsf(wf.y), th.y, qd);
        }
        red[tid] = qn;
        red[256 + tid] = qd;
        __syncthreads();
        if (tid < 128)
            g_Sen[(size_t)item * Hdim + tid] = make_float2(red[tid] + red[tid + 128],
                                                           red[256 + tid] + red[384 + tid]);
        __syncthreads();
    }
}

// ---------------- scan kernel: 1 CTA/batch, 512 threads -----------------------
// d = tid & 127, q = tid >> 7 (src quarter; warp-uniform)
// smem:
//   0      sPh  half [128 rows, pitch 130] 33280
//   33280  sSa  half [128 rows, pitch 130] 33280 -> 66560
//   66560  svF  float[128]   512 -> 67072   (fp32 state)
//   67072  sgs  float[128]   512 -> 67584
//   67584  svH  half[128]    256 -> 67840   (fp16 state for fast unfolds)
//   67840  red2 float2[512] 4096 -> 71936   (aliased as float[1024] in epilogue)
#define SCAN_SMEM 71936
#define PH_PITCH 130

__global__ __launch_bounds__(512, 1)
void ltc_scan(const float* __restrict__ h0,
              const float* __restrict__ amplitude, const float* __restrict__ omega,
              const float* __restrict__ phase_b,
              const float* __restrict__ alpha_p, const float* __restrict__ beta_p,
              float* __restrict__ out)
{
    extern __shared__ char smem[];
    __half*  sPh  = (__half*)smem;
    __half*  sSa  = (__half*)(smem + 33280);
    float*   svF  = (float*)(smem + 66560);
    float*   sgs  = (float*)(smem + 67072);
    __half2* svH2 = (__half2*)(smem + 67584);   // 64 half2
    float2*  red2 = (float2*)(smem + 67840);
    float*   redf = (float*)(smem + 67840);     // alias (epilogue)

    const int tid = threadIdx.x;
    const int b   = blockIdx.x;
    const int d   = tid & 127;       // dst
    const int q   = tid >> 7;        // src quarter (warp-uniform)
    const int p0  = q * 16;          // first src pair

    // ---- recurrent params into registers (half2)
    __half2 rp1[16], rc[16], rw[16], rwab[16];
    #pragma unroll
    for (int i = 0; i < 16; ++i) {
        int e = (p0 + i) * Hdim + d;
        rp1[i]  = g_RP1h[e];
        rc[i]   = g_RCh[e];
        rw[i]   = g_RWh[e];
        rwab[i] = __habs2(rw[i]);
    }

    // ---- epilogue weights into padded smem rows (pitch 130 halfs)
    {
        const __half2* ph2 = (const __half2*)g_Ph;
        const __half2* sa2 = (const __half2*)g_Sa;
        #pragma unroll 2
        for (int i = tid; i < (Hdim*Hdim)/2; i += 512) {
            int dd = i >> 6, jj = i & 63;
            ((__half2*)((char*)sPh + dd * (PH_PITCH*2)))[jj] = ph2[i];
            ((__half2*)((char*)sSa + dd * (PH_PITCH*2)))[jj] = sa2[i];
        }
    }
    if (tid < 128) {
        float v = h0[b * Hdim + tid];
        svF[tid] = v;
        ((__half*)svH2)[tid] = __float2half(v);
    }
    __syncthreads();

    const float alpha = *alpha_p;
    const float beta  = *beta_p;

    const float KN   = g_KN[d];
    const float KD   = g_KD[d];
    const float cmt  = g_CmT[d];
    const float aamp = alpha * amplitude[d];
    const float omg  = omega[d];
    const float phb  = phase_b[d];
    float vreg = svF[d];             // writer lanes keep the running state

    const int kh0 = q * 16;          // epilogue k quarter (in float2/half2 units)

    #pragma unroll 1
    for (int t = 0; t < Sdim; ++t) {
        float2 sen = g_Sen[(size_t)(b * Sdim + t) * Hdim + d];
        float N0 = KN + sen.x;
        float D0 = KD + sen.y;

        // ---- 4 fast unfolds: all-f16x2 inner loop, h2 accumulators
        #pragma unroll 1
        for (int u = 0; u < UNF_FAST; ++u) {
            __half2 qn2 = __floats2half2_rn(0.f, 0.f);
            __half2 qd2 = qn2;
            #pragma unroll
            for (int i = 0; i < 16; ++i) {
                __half2 vh  = svH2[p0 + i];                 // bcast LDS.32
                __half2 arg = __hfma2(rp1[i], vh, rc[i]);
                __half2 th  = ltc_tanh_h2(arg);
                qn2 = __hfma2(rw[i],   th, qn2);
                qd2 = __hfma2(rwab[i], th, qd2);
            }
            float2 qnf = __half22float2(qn2);
            float2 qdf = __half22float2(qd2);
            red2[tid] = make_float2(qnf.x + qnf.y, qdf.x + qdf.y);
            __syncthreads();
            if (tid < 128) {
                float2 r0 = red2[d], r1 = red2[d+128], r2 = red2[d+256], r3 = red2[d+384];
                float num = fmaf(cmt, vreg, N0 + r0.x + r1.x + r2.x + r3.x);
                float den = D0 + r0.y + r1.y + r2.y + r3.y;
                vreg = __fdividef(num, den);
                ((__half*)svH2)[d] = __float2half(vreg);
                if (u == UNF_FAST - 1) svF[d] = vreg;  // fp32 input for accurate unfold
            }
            __syncthreads();
        }

        // ---- final unfold: accurate fp32 args + tanh.f32 (reads svF)
        {
            const float2* sv2 = (const float2*)svF;
            float qn = 0.f, qd = 0.f;
            #pragma unroll
            for (int i = 0; i < 16; ++i) {
                float2 v2 = sv2[p0 + i];
                float2 a  = __half22float2(rp1[i]);
                float2 c  = __half22float2(rc[i]);
                float2 wf = __half22float2(rw[i]);
                float th0 = ltc_tanh_f32(fmaf(a.x, v2.x, c.x));
                float th1 = ltc_tanh_f32(fmaf(a.y, v2.y, c.y));
                qn = fmaf(wf.x, th0, qn);
                qn = fmaf(wf.y, th1, qn);
                qd = fmaf(fabsf(wf.x), th0, qd);
                qd = fmaf(fabsf(wf.y), th1, qd);
            }
            red2[tid] = make_float2(qn, qd);
            __syncthreads();
            if (tid < 128) {
                float2 r0 = red2[d], r1 = red2[d+128], r2 = red2[d+256], r3 = red2[d+384];
                float num = fmaf(cmt, vreg, N0 + r0.x + r1.x + r2.x + r3.x);
                float den = D0 + r0.y + r1.y + r2.y + r3.y;
                vreg = __fdividef(num, den);
                svF[d] = vreg;
                // sigmoid of PRE-pulse v for fused self-attend (error ~6e-6)
                sgs[d] = 0.5f + 0.5f * ltc_tanh_f32(0.5f * vreg);
            }
            __syncthreads();
        }

        // ---- FUSED epilogue: pulse matvec + self-attend matvec in one phase
        {
            float ph = 0.f, sa = 0.f;
            const __half2* prow = (const __half2*)(sPh + d * PH_PITCH) + kh0;
            const __half2* srow = (const __half2*)(sSa + d * PH_PITCH) + kh0;
            const float2* sv2 = (const float2*)svF + kh0;
            const float2* sg2 = (const float2*)sgs + kh0;
            #pragma unroll
            for (int j = 0; j < 16; ++j) {
                float2 wp = __half22float2(prow[j]);
                float2 ws = __half22float2(srow[j]);
                float2 v2 = sv2[j];
                float2 s2 = sg2[j];
                ph = fmaf(wp.x, v2.x, ph);
                ph = fmaf(wp.y, v2.y, ph);
                sa = fmaf(ws.x, s2.x, sa);
                sa = fmaf(ws.y, s2.y, sa);
            }
            redf[tid] = ph;
            redf[512 + tid] = sa;
        }
        __syncthreads();
        if (tid < 128) {
            float phi = redf[d] + redf[d+128] + redf[d+256] + redf[d+384] + phb;
            float sas = redf[512+d] + redf[512+d+128] + redf[512+d+256] + redf[512+d+384];
            vreg = fmaf(aamp, __sinf(fmaf(omg, (float)t, phi)), vreg);
            vreg = fmaf(beta, sas, vreg);
            svF[d] = vreg;
            ((__half*)svH2)[d] = __float2half(vreg);   // state for next step
            out[(size_t)(b * Sdim + t) * Hdim + d] = vreg;
        }
        __syncthreads();
    }

    if (tid < 128)
        out[(size_t)Bdim * Sdim * Hdim + b * Hdim + d] = vreg;
}

// ---------------- launch ----------------
extern "C" void kernel_launch(void* const* d_in, const int* in_sizes, int n_in,
                              void* d_out, int out_size)
{
    const float* x        = (const float*)d_in[0];
    const float* h0       = (const float*)d_in[1];
    const float* input_w  = (const float*)d_in[2];
    const float* input_b  = (const float*)d_in[3];
    const float* gleak    = (const float*)d_in[4];
    const float* vleak    = (const float*)d_in[5];
    const float* cm       = (const float*)d_in[6];
    const float* sigma    = (const float*)d_in[7];
    const float* mu       = (const float*)d_in[8];
    const float* w        = (const float*)d_in[9];
    const float* erev     = (const float*)d_in[10];
    const float* s_sigma  = (const float*)d_in[11];
    const float* s_mu     = (const float*)d_in[12];
    const float* s_w      = (const float*)d_in[13];
    const float* s_erev   = (const float*)d_in[14];
    const float* amplitude= (const float*)d_in[15];
    const float* omega    = (const float*)d_in[16];
    const float* phase_W  = (const float*)d_in[17];
    const float* phase_b  = (const float*)d_in[18];
    const float* alpha    = (const float*)d_in[19];
    const float* sa_W     = (const float*)d_in[20];
    const float* beta     = (const float*)d_in[21];
    float* out = (float*)d_out;

    ltc_pre1<<<64, 256>>>(sigma, mu, w, erev, s_sigma, s_mu, s_w, s_erev,
                          input_w, input_b, phase_W, sa_W);
    ltc_pre2<<<1, 128>>>(gleak, vleak, cm, w, erev, s_w, s_erev);

    cudaFuncSetAttribute(ltc_sensory, cudaFuncAttributeMaxDynamicSharedMemorySize, SEN_SMEM);
    ltc_sensory<<<148, 256, SEN_SMEM>>>(x);

    cudaFuncSetAttribute(ltc_scan, cudaFuncAttributeMaxDynamicSharedMemorySize, SCAN_SMEM);
    ltc_scan<<<Bdim, 512, SCAN_SMEM>>>(h0, amplitude, omega, phase_b,
                                       alpha, beta, out);
}